// round 13
// baseline (speedup 1.0000x reference)
#include <cuda_runtime.h>

// Slice_windows: (32,1,1024,1024) f32 -> (32,8) f32
//
// R13: barrier-free column cascade.
//  - 1024 CTAs x 256 threads; CTA = 32-row x 1024-col strip (128 KB).
//  - Thread owns 4 columns, walks 16 row-pairs: 2 LDG.128 per pair, all
//    independent; k=2 and k=4 entropy fully thread-local; k=8/16/32 via
//    rare shuffle folds (8 shuffles per 16 iters, off the load path).
//    NO smem, NO __syncthreads in the hot loop.
//  - 32rx64c half-sums exported to g_half; k=64/128/256 + all means done
//    by the last-arriving CTA (deterministic fixed-order reduction).

#define NBATCH   32
#define NCTAS    1024          // 32 strips/image
#define NTHREADS 256
#define NLVL_IN  5             // in-CTA levels k=2..32

__device__ float g_parts[NLVL_IN * NCTAS]; // [level][cta]
__device__ float g_half[NBATCH * 512];     // [b][strip(32)][colwin64(16)]
__device__ int   g_count = 0;

__device__ __forceinline__ float plogp(float p) {
    // p * log2(p), 0 at p == 0
    return (p > 0.f) ? p * __log2f(p) : 0.f;
}
// returns plogp(p) + plogp(1-p)  (<= 0); entropy = -ent
__device__ __forceinline__ float ent(float s, float inv_n) {
    const float p = s * inv_n;
    return plogp(p) + plogp(1.f - p);
}

__global__ void __launch_bounds__(NTHREADS, 4)
slice_windows(const float* __restrict__ x, float* __restrict__ out)
{
    __shared__ float s_wp[8][NLVL_IN];
    __shared__ float s_f[NTHREADS][3];
    __shared__ bool  is_last;

    const int tid  = threadIdx.x;
    const int bid  = blockIdx.x;
    const int b    = bid >> 5;            // image
    const int sr   = bid & 31;            // strip row (32 rows each)
    const int lane = tid & 31;

    const float* __restrict__ p0 =
        x + (size_t)b * (1024 * 1024) + (size_t)(sr * 32) * 1024 + tid * 4;

    float e2 = 0.f, e4 = 0.f, e8 = 0.f, e16 = 0.f, e32 = 0.f;
    float c4 = 0.f, c8 = 0.f, c16 = 0.f, c32 = 0.f;
    float h64 = 0.f;

#pragma unroll
    for (int i = 0; i < 16; ++i) {
        const float4 a0 = *(const float4*)(p0 + (size_t)(2 * i) * 1024);
        const float4 a1 = *(const float4*)(p0 + (size_t)(2 * i + 1) * 1024);
        const float s0 = (a0.x + a0.y) + (a1.x + a1.y);
        const float s1 = (a0.z + a0.w) + (a1.z + a1.w);
        e2 += ent(s0, 0.25f) + ent(s1, 0.25f);          // two k=2 windows
        const float r4 = s0 + s1;                       // 2r x 4c
        if ((i & 1) == 0) { c4 = r4; }
        else {
            const float v4 = c4 + r4;                   // 4x4 window
            e4 += ent(v4, 1.f / 16.f);
            if ((i & 2) == 0) { c8 = v4; }
            else {
                const float w8 = c8 + v4;               // 8r x 4c
                const float S8 = w8 + __shfl_xor_sync(0xffffffffu, w8, 1);
                e8 += ent(S8, 1.f / 64.f);              // dup x2
                if ((i & 4) == 0) { c16 = S8; }
                else {
                    const float v16 = c16 + S8;         // 16r x 8c
                    const float S16 = v16 + __shfl_xor_sync(0xffffffffu, v16, 2);
                    e16 += ent(S16, 1.f / 256.f);       // dup x4
                    if ((i & 8) == 0) { c32 = S16; }
                    else {
                        const float v32 = c32 + S16;    // 32r x 16c
                        const float S32 = v32 + __shfl_xor_sync(0xffffffffu, v32, 4);
                        e32 += ent(S32, 1.f / 1024.f);  // dup x8
                        h64 = S32 + __shfl_xor_sync(0xffffffffu, S32, 8); // 32r x 64c
                    }
                }
            }
        }
    }

    // export half-sums: one per 16-lane fold group
    if ((lane & 15) == 0)
        g_half[b * 512 + sr * 16 + (tid >> 4)] = h64;

    // fold duplication, butterfly-reduce the 5 entropy accumulators
    e8  *= 0.5f;
    e16 *= 0.25f;
    e32 *= 0.125f;
#pragma unroll
    for (int o = 16; o > 0; o >>= 1) {
        e2  += __shfl_xor_sync(0xffffffffu, e2,  o);
        e4  += __shfl_xor_sync(0xffffffffu, e4,  o);
        e8  += __shfl_xor_sync(0xffffffffu, e8,  o);
        e16 += __shfl_xor_sync(0xffffffffu, e16, o);
        e32 += __shfl_xor_sync(0xffffffffu, e32, o);
    }
    const int warp = tid >> 5;
    if (lane == 0) {
        s_wp[warp][0] = e2;  s_wp[warp][1] = e4;  s_wp[warp][2] = e8;
        s_wp[warp][3] = e16; s_wp[warp][4] = e32;
    }
    __syncthreads();
    if (tid < NLVL_IN) {
        float s = 0.f;
#pragma unroll
        for (int w = 0; w < 8; w++) s += s_wp[w][tid];
        g_parts[tid * NCTAS + bid] = s;
    }

    // ---- fused finalize by last-arriving CTA
    __threadfence();
    if (tid == 0) {
        const int prev = atomicAdd(&g_count, 1);
        is_last = (prev == NCTAS - 1);
    }
    __syncthreads();
    if (!is_last) return;

    {
        const int bb = tid >> 3;       // image 0..31
        const int l  = tid & 7;
        // levels k=2..32 from per-CTA partials (32 contiguous per image)
        if (l < NLVL_IN) {
            const float* gp = g_parts + l * NCTAS + bb * 32;
            float s = 0.f;
#pragma unroll
            for (int t = 0; t < 32; t++) s += __ldcg(gp + t);
            const int d = 1024 >> (l + 1);
            out[bb * 8 + l] = -s / (float)(d * d);
        }

        // levels k=64/128/256 from half-sums (32r x 64c blocks, [16][16] grid)
        const float* h = g_half + bb * 512;
        const int g = l;               // window-group 0..7
        float se64 = 0.f, se128 = 0.f, se256 = 0.f;
        // k=64: 16x16 windows, window = 2 vertical halves; rows {g, g+8}
#pragma unroll
        for (int rr = 0; rr < 2; rr++) {
            const int r = g + rr * 8;
#pragma unroll
            for (int c = 0; c < 16; c++) {
                const float S = __ldcg(h + (2 * r) * 16 + c)
                              + __ldcg(h + (2 * r + 1) * 16 + c);
                se64 += ent(S, 1.f / 4096.f);
            }
        }
        // k=128: 8x8 windows, window = 4 strips x 2 colwins; row g
#pragma unroll
        for (int c = 0; c < 8; c++) {
            float S = 0.f;
#pragma unroll
            for (int i = 0; i < 4; i++)
#pragma unroll
                for (int j = 0; j < 2; j++)
                    S += __ldcg(h + (4 * g + i) * 16 + 2 * c + j);
            se128 += ent(S, 1.f / 16384.f);
        }
        // k=256: 4x4 windows, window = 8 strips x 4 colwins; 2 per thread
#pragma unroll
        for (int wi = 0; wi < 2; wi++) {
            const int w = 2 * g + wi;
            const int r = w >> 2, c = w & 3;
            float S = 0.f;
#pragma unroll
            for (int i = 0; i < 8; i++)
#pragma unroll
                for (int j = 0; j < 4; j++)
                    S += __ldcg(h + (8 * r + i) * 16 + 4 * c + j);
            se256 += ent(S, 1.f / 65536.f);
        }
        s_f[tid][0] = se64; s_f[tid][1] = se128; s_f[tid][2] = se256;
    }
    __syncthreads();
    if (tid < 96) {
        const int bb = tid & 31;
        const int lv = tid >> 5;       // 0:k=64 1:k=128 2:k=256
        float s = 0.f;
#pragma unroll
        for (int g = 0; g < 8; g++) s += s_f[bb * 8 + g][lv];
        const float div = (lv == 0) ? 256.f : (lv == 1) ? 64.f : 16.f;
        out[bb * 8 + 5 + lv] = -s / div;
    }
    if (tid == 0) g_count = 0;         // reset for graph replay
}

extern "C" void kernel_launch(void* const* d_in, const int* in_sizes, int n_in,
                              void* d_out, int out_size)
{
    (void)in_sizes; (void)n_in; (void)out_size;
    const float* x = (const float*)d_in[0];
    float* out = (float*)d_out;
    slice_windows<<<NCTAS, NTHREADS>>>(x, out);
}

// round 14
// speedup vs baseline: 1.3826x; 1.3826x over previous
#include <cuda_runtime.h>
#include <cstdint>

// Slice_windows: (32,1,1024,1024) f32 -> (32,8) f32
//
// R14: TMA bulk-copy pipeline. Load issue is decoupled from warp execution:
// cp.async.bulk (async proxy) streams 16KB stages into a 4-deep smem ring;
// consumers compute from smem and can stall without throttling DRAM.
//  - 512 CTAs x 256 thr; CTA = 64x1024 strip (contiguous => no tensormap).
//  - Per stage (4 rows): k=2 + k=4 in registers from smem; k=4 sums -> plane.
//  - Pyramid k=8..64 on the 16x256 k=4 plane; k=64 sums -> g_64.
//  - k=128/256 + all means by last-arriving CTA (fixed order, deterministic).

#define NBATCH   32
#define NCTAS    512
#define NTHREADS 256
#define STAGES   4
#define STAGE_BYTES 16384      // 4 rows x 1024 f32
#define ITERS    16            // 64 rows / 4

// smem layout (bytes):
//   [0,32)        4 mbarriers
//   [128,65664)   4 stages x 16384
//   then floats:  k4 plane 16x256 (4096), pyramid 1360, warp partials 48, flag
#define SMEM_BYTES (128 + STAGES * STAGE_BYTES + (4096 + 1360 + 48 + 4) * 4)

__device__ float g_parts[6 * NCTAS];   // [level][cta], k=2..64
__device__ float g_64[NCTAS * 16];     // per-strip k=64 sums (16 per strip)
__device__ int   g_count = 0;

__device__ __forceinline__ float plogp(float p) {
    return (p > 0.f) ? p * __log2f(p) : 0.f;   // p*log2 p, 0 at p==0
}
__device__ __forceinline__ float ent(float s, float inv_n) {
    const float p = s * inv_n;
    return plogp(p) + plogp(1.f - p);          // <= 0; entropy = -ent
}

__device__ __forceinline__ uint32_t s2u(const void* p) {
    uint32_t a;
    asm("{ .reg .u64 t; cvta.to.shared.u64 t, %1; cvt.u32.u64 %0, t; }"
        : "=r"(a) : "l"(p));
    return a;
}
__device__ __forceinline__ void mbar_init(uint32_t a, uint32_t cnt) {
    asm volatile("mbarrier.init.shared.b64 [%0], %1;" :: "r"(a), "r"(cnt) : "memory");
}
__device__ __forceinline__ void mbar_expect_tx(uint32_t a, uint32_t tx) {
    asm volatile("mbarrier.arrive.expect_tx.shared.b64 _, [%0], %1;"
                 :: "r"(a), "r"(tx) : "memory");
}
__device__ __forceinline__ void bulk_g2s(uint32_t dst, const void* src,
                                         uint32_t bytes, uint32_t mbar) {
    asm volatile(
        "cp.async.bulk.shared::cluster.global.mbarrier::complete_tx::bytes "
        "[%0], [%1], %2, [%3];"
        :: "r"(dst), "l"(src), "r"(bytes), "r"(mbar) : "memory");
}
__device__ __forceinline__ void mbar_wait(uint32_t a, uint32_t ph) {
    uint32_t done;
    do {
        asm volatile(
            "{\n\t.reg .pred p;\n\t"
            "mbarrier.try_wait.parity.acquire.cta.shared::cta.b64 p, [%1], %2;\n\t"
            "selp.b32 %0, 1, 0, p;\n\t}"
            : "=r"(done) : "r"(a), "r"(ph) : "memory");
    } while (!done);
}

__global__ void __launch_bounds__(NTHREADS, 2)
slice_windows(const float* __restrict__ x, float* __restrict__ out)
{
    extern __shared__ __align__(128) unsigned char smraw[];
    uint64_t* mb   = (uint64_t*)smraw;
    float*    stg  = (float*)(smraw + 128);
    float*    k4p  = (float*)(smraw + 128 + STAGES * STAGE_BYTES);
    float*    pyr  = k4p + 4096;          // k8(1024) k16(256) k32(64) k64(16)
    float*    s_wp = pyr + 1360;          // 8 warps x 6
    int*      flag = (int*)(s_wp + 48);

    const int tid  = threadIdx.x;
    const int bid  = blockIdx.x;
    const int b    = bid >> 4;            // image
    const int sr   = bid & 15;            // strip (64 rows)
    const float* __restrict__ gsrc = x + (size_t)b * 1048576 + (size_t)sr * 65536;

    const uint32_t mb_u  = s2u(mb);
    const uint32_t stg_u = s2u(stg);

    if (tid == 0) {
#pragma unroll
        for (int s = 0; s < STAGES; s++) mbar_init(mb_u + 8 * s, 1);
    }
    __syncthreads();
    if (tid == 0) {
#pragma unroll
        for (int s = 0; s < STAGES; s++) {
            mbar_expect_tx(mb_u + 8 * s, STAGE_BYTES);
            bulk_g2s(stg_u + s * STAGE_BYTES, gsrc + s * 4096,
                     STAGE_BYTES, mb_u + 8 * s);
        }
    }

    float e[6];
#pragma unroll
    for (int l = 0; l < 6; l++) e[l] = 0.f;

    // ---- Streaming loop: 16 stages of 4 rows.
    for (int it = 0; it < ITERS; ++it) {
        const int s  = it & 3;
        const int ph = (it >> 2) & 1;
        mbar_wait(mb_u + 8 * s, ph);

        const float* st = stg + s * 4096 + tid * 4;
        const float4 a0 = *(const float4*)(st);
        const float4 a1 = *(const float4*)(st + 1024);
        const float4 a2 = *(const float4*)(st + 2048);
        const float4 a3 = *(const float4*)(st + 3072);
        const float s00 = (a0.x + a0.y) + (a1.x + a1.y);
        const float s01 = (a0.z + a0.w) + (a1.z + a1.w);
        const float s10 = (a2.x + a2.y) + (a3.x + a3.y);
        const float s11 = (a2.z + a2.w) + (a3.z + a3.w);
        e[0] += ent(s00, .25f) + ent(s01, .25f) + ent(s10, .25f) + ent(s11, .25f);
        const float S4 = (s00 + s01) + (s10 + s11);
        e[1] += ent(S4, .0625f);
        k4p[it * 256 + tid] = S4;

        __syncthreads();                   // all reads of stage s done
        if (tid == 0 && it + STAGES < ITERS) {
            mbar_expect_tx(mb_u + 8 * s, STAGE_BYTES);
            bulk_g2s(stg_u + s * STAGE_BYTES, gsrc + (it + STAGES) * 4096,
                     STAGE_BYTES, mb_u + 8 * s);
        }
    }
    // k4p fully written (last loop iteration ends with __syncthreads).

    // ---- Pyramid on 16x256 k=4 plane: k=8,16,32,64.
    {
        const float* inp = k4p;
        float* outp = pyr;
        int in_w = 256, in_h = 16;
#pragma unroll
        for (int l = 2; l < 6; ++l) {
            const int out_w = in_w >> 1, out_h = in_h >> 1;
            const int nout = out_w * out_h;
            const float inv_n = 1.0f / (float)(1 << (2 * (l + 1)));
            for (int i = tid; i < nout; i += NTHREADS) {
                const int oy = i / out_w;
                const int ox = i - oy * out_w;
                const float* r0 = inp + (2 * oy) * in_w + 2 * ox;
                const float* r1 = r0 + in_w;
                const float sN = (r0[0] + r0[1]) + (r1[0] + r1[1]);
                e[l] += ent(sN, inv_n);
                outp[i] = sN;
                if (l == 5) g_64[bid * 16 + i] = sN;   // 1x16 k=64 sums
            }
            __syncthreads();
            inp = outp;
            outp += nout;
            in_w = out_w; in_h = out_h;
        }
    }

    // ---- Block-reduce the 6 entropy accumulators (8 warps).
    const int lane = tid & 31;
    const int warp = tid >> 5;
#pragma unroll
    for (int l = 0; l < 6; l++) {
        float v = e[l];
#pragma unroll
        for (int o = 16; o > 0; o >>= 1)
            v += __shfl_down_sync(0xffffffffu, v, o);
        if (lane == 0) s_wp[warp * 6 + l] = v;
    }
    __syncthreads();
    if (tid < 6) {
        float s = 0.f;
#pragma unroll
        for (int w = 0; w < 8; w++) s += s_wp[w * 6 + tid];
        g_parts[tid * NCTAS + bid] = s;
    }

    // ---- Fused finalize by last-arriving CTA.
    __threadfence();
    if (tid == 0) {
        const int prev = atomicAdd(&g_count, 1);
        *flag = (prev == NCTAS - 1) ? 1 : 0;
    }
    __syncthreads();
    if (!*flag) return;

    {
        const int bb = tid >> 3;          // image 0..31
        const int l  = tid & 7;
        if (l < 6) {
            // k=2..64: sum this image's 16 strip partials
            const float* gp = g_parts + l * NCTAS + bb * 16;
            float s = 0.f;
#pragma unroll
            for (int t = 0; t < 16; t++) s += __ldcg(gp + t);
            const int d = 1024 >> (l + 1);
            out[bb * 8 + l] = -s / (float)(d * d);
        } else if (l == 6) {
            // k=128: 8x8 windows of 2x2 k=64 sums (grid 16 strips x 16 cols)
            const float* G = g_64 + bb * 256;
            float s = 0.f;
            for (int wy = 0; wy < 8; wy++)
#pragma unroll
                for (int wx = 0; wx < 8; wx++) {
                    const float S = __ldcg(G + (2 * wy) * 16 + 2 * wx)
                                  + __ldcg(G + (2 * wy) * 16 + 2 * wx + 1)
                                  + __ldcg(G + (2 * wy + 1) * 16 + 2 * wx)
                                  + __ldcg(G + (2 * wy + 1) * 16 + 2 * wx + 1);
                    s += ent(S, 1.f / 16384.f);
                }
            out[bb * 8 + 6] = -s / 64.f;
        } else {
            // k=256: 4x4 windows of 4x4 k=64 sums
            const float* G = g_64 + bb * 256;
            float s = 0.f;
            for (int wy = 0; wy < 4; wy++)
#pragma unroll
                for (int wx = 0; wx < 4; wx++) {
                    float S = 0.f;
#pragma unroll
                    for (int i = 0; i < 4; i++)
#pragma unroll
                        for (int j = 0; j < 4; j++)
                            S += __ldcg(G + (4 * wy + i) * 16 + 4 * wx + j);
                    s += ent(S, 1.f / 65536.f);
                }
            out[bb * 8 + 7] = -s / 16.f;
        }
    }
    if (tid == 0) g_count = 0;            // reset for graph replay
}

extern "C" void kernel_launch(void* const* d_in, const int* in_sizes, int n_in,
                              void* d_out, int out_size)
{
    (void)in_sizes; (void)n_in; (void)out_size;
    const float* x = (const float*)d_in[0];
    float* out = (float*)d_out;

    cudaFuncSetAttribute(slice_windows,
                         cudaFuncAttributeMaxDynamicSharedMemorySize, SMEM_BYTES);
    slice_windows<<<NCTAS, NTHREADS, SMEM_BYTES>>>(x, out);
}

// round 15
// speedup vs baseline: 1.8520x; 1.3395x over previous
#include <cuda_runtime.h>

// Slice_windows: (32,1,1024,1024) f32 -> (32,8) f32
//
// R15 = R3 main kernel EXACTLY (measured best: 28.0us kernel; 512 thr,
// lb(512,4) => 32 regs, 2048 thr/SM) + fused finalize tail (removes the
// separate finalize launch, ~1.3us of graph overhead).
//  - One CTA per 256x256 tile (512 CTAs).
//  - Gmem pass: each thread 4x4 blocks -> k=2 entropies + k=4 sum/entropy in
//    registers; 64x64 k=4 sums -> smem (21.8 KB).
//  - Smem pyramid k=8..256.
//  - Last-arriving CTA reduces the 512x8 partials in fixed order.

#define NLEVELS 8
#define TILES_PER_IMG 16
#define NBATCH 32
#define NBLOCKS (NBATCH * TILES_PER_IMG)
#define NTHREADS 512

// pyramid: 64^2 + 32^2 + 16^2 + 8^2 + 4^2 + 2^2 + 1 = 5461 floats (21844 B)
#define SMEM_FLOATS 5461

__device__ float g_partials[NBLOCKS * NLEVELS];
__device__ int   g_count = 0;

__device__ __forceinline__ float plogp(float p) {
    // p * log2(p), 0 at p == 0
    return (p > 0.f) ? p * __log2f(p) : 0.f;
}
__device__ __forceinline__ float ent(float s, float inv_n) {
    const float p = s * inv_n;
    return plogp(p) + plogp(1.f - p);
}

__global__ void __launch_bounds__(NTHREADS, 4)
slice_windows_fused(const float* __restrict__ x, float* __restrict__ out)
{
    __shared__ float sm[SMEM_FLOATS];
    __shared__ bool  is_last;

    const int tid  = threadIdx.x;
    const int bid  = blockIdx.x;
    const int b    = bid >> 4;
    const int tile = bid & 15;
    const int row0 = (tile >> 2) * 256;
    const int col0 = (tile & 3) * 256;
    const float* __restrict__ img = x + (size_t)b * 1024 * 1024;

    float eacc[NLEVELS];
#pragma unroll
    for (int l = 0; l < NLEVELS; l++) eacc[l] = 0.f;

    // ---- Gmem pass: k=2 and k=4 in registers; store 64x64 k=4 sums to smem.
    {
        const int c4 = tid & 63;          // 4-col group: 0..63
        const int r  = tid >> 6;          // 0..7
        const float* base = img + (size_t)row0 * 1024 + col0 + c4 * 4;
#pragma unroll
        for (int it = 0; it < 8; ++it) {
            const int orow = it * 8 + r;                // k=4 output row 0..63
            const float* p = base + (size_t)orow * 4096;
            const float4 a0 = *(const float4*)(p);
            const float4 a1 = *(const float4*)(p + 1024);
            const float4 a2 = *(const float4*)(p + 2048);
            const float4 a3 = *(const float4*)(p + 3072);
            const float s00 = (a0.x + a0.y) + (a1.x + a1.y);
            const float s01 = (a0.z + a0.w) + (a1.z + a1.w);
            const float s10 = (a2.x + a2.y) + (a3.x + a3.y);
            const float s11 = (a2.z + a2.w) + (a3.z + a3.w);
            eacc[0] -= ent(s00, .25f) + ent(s01, .25f)
                     + ent(s10, .25f) + ent(s11, .25f);
            const float S = (s00 + s01) + (s10 + s11);
            eacc[1] -= ent(S, .0625f);
            sm[orow * 64 + c4] = S;
        }
    }
    __syncthreads();

    // ---- Pyramid in smem: levels l=2..7 (k=8..256), 64x64 -> 1x1.
    int in_off = 0, in_dim = 64, out_off = 4096;
#pragma unroll
    for (int l = 2; l < NLEVELS; l++) {
        const int out_dim = in_dim >> 1;
        const int nout = out_dim * out_dim;
        const float inv_n = 1.0f / (float)(1 << (2 * (l + 1)));  // 1/k^2
        for (int i = tid; i < nout; i += NTHREADS) {
            const int oy = i / out_dim;
            const int ox = i - oy * out_dim;
            const float* rp0 = sm + in_off + (2 * oy) * in_dim + 2 * ox;
            const float* rp1 = rp0 + in_dim;
            const float s = (rp0[0] + rp0[1]) + (rp1[0] + rp1[1]);
            eacc[l] -= ent(s, inv_n);
            sm[out_off + i] = s;
        }
        __syncthreads();
        in_off = out_off;
        in_dim = out_dim;
        out_off += nout;
    }
    // Region sm[0..4095] is dead now -> reuse for the block reduction.

    // ---- Block-reduce the 8 per-thread entropy accumulators (16 warps).
    const int lane = tid & 31;
    const int warp = tid >> 5;
#pragma unroll
    for (int l = 0; l < NLEVELS; l++) {
        float v = eacc[l];
#pragma unroll
        for (int o = 16; o > 0; o >>= 1)
            v += __shfl_down_sync(0xffffffffu, v, o);
        if (lane == 0) sm[warp * NLEVELS + l] = v;
    }
    __syncthreads();
    if (tid < NLEVELS) {
        float s = 0.f;
#pragma unroll
        for (int w = 0; w < 16; w++) s += sm[w * NLEVELS + tid];
        g_partials[bid * NLEVELS + tid] = s;
    }

    // ---- Fused finalize: last-arriving CTA reduces all partials.
    __threadfence();
    if (tid == 0) {
        const int prev = atomicAdd(&g_count, 1);
        is_last = (prev == NBLOCKS - 1);
    }
    __syncthreads();
    if (is_last) {
        if (tid < NBATCH * NLEVELS) {
            const int bb = tid >> 3;
            const int l  = tid & 7;
            float s = 0.f;
#pragma unroll
            for (int t = 0; t < TILES_PER_IMG; t++)
                s += __ldcg(&g_partials[(bb * TILES_PER_IMG + t) * NLEVELS + l]);
            const int d = 1024 >> (l + 1);   // windows per side, k = 2^(l+1)
            out[bb * NLEVELS + l] = s / (float)(d * d);
        }
        if (tid == 0) g_count = 0;           // reset for graph replay
    }
}

extern "C" void kernel_launch(void* const* d_in, const int* in_sizes, int n_in,
                              void* d_out, int out_size)
{
    (void)in_sizes; (void)n_in; (void)out_size;
    const float* x = (const float*)d_in[0];
    float* out = (float*)d_out;
    slice_windows_fused<<<NBLOCKS, NTHREADS>>>(x, out);
}